// round 14
// baseline (speedup 1.0000x reference)
#include <cuda_runtime.h>
#include <cuda_fp16.h>
#include <cstdint>
#include <math.h>

// ============================================================
// Problem constants
// ============================================================
#define B_ROWS 8192
#define D_DIM  1024
#define K_CB   4096
#define L_STEPS 8
#define RES_TH 1e-3f
#define THR    0.40f

// GEMM tiling: CTA 256x128, 512 threads, 16 warps (4M x 4N), warp tile 64x32
#define BM 256
#define BN 128
#define BK 64
#define NT    (K_CB / BN)     // 32
#define NKCH  (D_DIM / BK)    // 16
#define NSTAGE 4
#define A_BYTES (BM * BK * 2)
#define B_BYTES (BN * BK * 2)
#define STAGE_BYTES (A_BYTES + B_BYTES)        // 49152
#define SMEM_TOTAL  (NSTAGE * STAGE_BYTES)     // 196608

// ============================================================
// Device scratch — every array <= 32 MB
// ============================================================
__device__ __align__(128) float  g_resid[B_ROWS * D_DIM];            // 32 MB
__device__ __align__(128) __half g_rh0[B_ROWS * D_DIM];              // 16 MB
__device__ __align__(128) __half g_cb0[K_CB * D_DIM];                // 8 MB
#define SC_CHUNK_ROWS 2048
__device__ __align__(128) float g_sc0[SC_CHUNK_ROWS * K_CB];         // 32 MB x4
__device__ __align__(128) float g_sc1[SC_CHUNK_ROWS * K_CB];
__device__ __align__(128) float g_sc2[SC_CHUNK_ROWS * K_CB];
__device__ __align__(128) float g_sc3[SC_CHUNK_ROWS * K_CB];
__device__ __align__(128) float g_G0[SC_CHUNK_ROWS * K_CB];          // 32 MB x2
__device__ __align__(128) float g_G1[SC_CHUNK_ROWS * K_CB];

__device__ float g_t1v[B_ROWS * NT];
__device__ int   g_t1i[B_ROWS * NT];
__device__ float g_t2v[B_ROWS * NT];
__device__ int   g_t2i[B_ROWS * NT];
__device__ float g_rowt1v[B_ROWS];
__device__ int   g_rowt1i[B_ROWS];
__device__ float g_rowt2v[B_ROWS];
__device__ float g_norm2[B_ROWS];
__device__ int   g_active[B_ROWS];
__device__ int   g_indices[B_ROWS * L_STEPS];
__device__ int   g_choice[B_ROWS];
__device__ int   g_flagcnt;
__device__ int   g_flaglist[B_ROWS];

__device__ __forceinline__ float* score_row(int r) {
    int c = r >> 11;
    float* b = (c == 0) ? g_sc0 : (c == 1) ? g_sc1 : (c == 2) ? g_sc2 : g_sc3;
    return b + (size_t)(r & (SC_CHUNK_ROWS - 1)) * K_CB;
}
__device__ __forceinline__ float* G_row(int k) {
    float* b = (k >> 11) ? g_G1 : g_G0;
    return b + (size_t)(k & (SC_CHUNK_ROWS - 1)) * K_CB;
}

// ============================================================
// PTX helpers
// ============================================================
__device__ __forceinline__ uint32_t smem_u32(const void* p) {
    uint32_t a;
    asm("{ .reg .u64 t; cvta.to.shared.u64 t, %1; cvt.u32.u64 %0, t; }"
        : "=r"(a) : "l"(p));
    return a;
}
__device__ __forceinline__ void cp16(uint32_t s, const void* g) {
    asm volatile("cp.async.cg.shared.global [%0], [%1], 16;" :: "r"(s), "l"(g));
}
#define CP_COMMIT() asm volatile("cp.async.commit_group;" ::: "memory")
#define CP_WAIT(n)  asm volatile("cp.async.wait_group %0;" :: "n"(n) : "memory")

__device__ __forceinline__ void ldsm4(uint32_t* r, uint32_t addr) {
    asm volatile("ldmatrix.sync.aligned.m8n8.x4.shared.b16 {%0,%1,%2,%3}, [%4];"
        : "=r"(r[0]), "=r"(r[1]), "=r"(r[2]), "=r"(r[3]) : "r"(addr));
}
__device__ __forceinline__ void mma16816(float* c, const uint32_t* a, const uint32_t* b) {
    asm volatile(
        "mma.sync.aligned.m16n8k16.row.col.f32.f16.f16.f32 "
        "{%0,%1,%2,%3}, {%4,%5,%6,%7}, {%8,%9}, {%0,%1,%2,%3};"
        : "+f"(c[0]), "+f"(c[1]), "+f"(c[2]), "+f"(c[3])
        : "r"(a[0]), "r"(a[1]), "r"(a[2]), "r"(a[3]), "r"(b[0]), "r"(b[1]));
}
__device__ __forceinline__ uint32_t sw_addr(uint32_t base, int row, int unit) {
    return base + (uint32_t)(row * 128) + (uint32_t)((unit ^ (row & 7)) << 4);
}

struct Top2 { float v1; int i1; float v2; int i2; };
__device__ __forceinline__ void t2_insert(Top2& t, float v, int c) {
    if (v > t.v1 || (v == t.v1 && c < t.i1)) {
        t.v2 = t.v1; t.i2 = t.i1; t.v1 = v; t.i1 = c;
    } else if (v > t.v2 || (v == t.v2 && c < t.i2)) {
        t.v2 = v; t.i2 = c;
    }
}
__device__ __forceinline__ void t2_merge(Top2& a, const Top2& b) {
    if (b.v1 > a.v1 || (b.v1 == a.v1 && b.i1 < a.i1)) {
        if (a.v1 > b.v2 || (a.v1 == b.v2 && a.i1 < b.i2)) { a.v2 = a.v1; a.i2 = a.i1; }
        else { a.v2 = b.v2; a.i2 = b.i2; }
        a.v1 = b.v1; a.i1 = b.i1;
    } else {
        if (b.v1 > a.v2 || (b.v1 == a.v2 && b.i1 < a.i2)) { a.v2 = b.v1; a.i2 = b.i1; }
    }
}

// ============================================================
// Unified GEMM: MODE 0 -> scores + per-tile top-2; MODE 1 -> Gram fp32
// MODE 1 computes only tiles with tileN >= 2*tileM; mirror fills rest.
// ============================================================
__device__ __forceinline__ void fill_stage(uint32_t st, const __half* Ag,
                                           int tileM, int tileN, int kc, int tid) {
    const __half* a0 = Ag + ((size_t)tileM * BM) * D_DIM + kc * BK;
    const __half* b0 = g_cb0 + ((size_t)tileN * BN) * D_DIM + kc * BK;
    #pragma unroll
    for (int i = 0; i < 4; i++) {
        int c = tid + i * 512;
        int row = c >> 3, u = c & 7;
        uint32_t sw = (uint32_t)(row * 128) + (uint32_t)((u ^ (row & 7)) << 4);
        cp16(st + sw, a0 + (size_t)row * D_DIM + (u << 3));
    }
    #pragma unroll
    for (int i = 0; i < 2; i++) {
        int c = tid + i * 512;
        int row = c >> 3, u = c & 7;
        uint32_t sw = (uint32_t)(row * 128) + (uint32_t)((u ^ (row & 7)) << 4);
        cp16(st + A_BYTES + sw, b0 + (size_t)row * D_DIM + (u << 3));
    }
}

template <int MODE>
__global__ void __launch_bounds__(512, 1) gemm_kernel() {
    extern __shared__ char smem[];
    uint32_t sb = smem_u32(smem);
    const int tid = threadIdx.x;
    const int tileM = blockIdx.x, tileN = blockIdx.y;
    const int wid = tid >> 5, lane = tid & 31;
    const int warpM = wid >> 2, warpN = wid & 3;
    const int grp = lane >> 2, qc = lane & 3;

    if (MODE == 1 && tileN < 2 * tileM) return;   // symmetry: skip lower wedge

    const __half* Ag = (MODE == 0) ? g_rh0 : g_cb0;

    if (MODE == 0 && tileM == 0 && tileN == 0 && tid == 0) g_flagcnt = 0;

    float acc[4][4][4];
    #pragma unroll
    for (int mi = 0; mi < 4; mi++)
        #pragma unroll
        for (int ni = 0; ni < 4; ni++)
            #pragma unroll
            for (int j = 0; j < 4; j++) acc[mi][ni][j] = 0.f;

    fill_stage(sb, Ag, tileM, tileN, 0, tid);                      CP_COMMIT();
    fill_stage(sb + STAGE_BYTES, Ag, tileM, tileN, 1, tid);        CP_COMMIT();
    fill_stage(sb + 2 * STAGE_BYTES, Ag, tileM, tileN, 2, tid);    CP_COMMIT();

    #pragma unroll 1
    for (int kc = 0; kc < NKCH; kc++) {
        if (kc < NKCH - 2)      { CP_WAIT(2); }
        else if (kc == NKCH - 2){ CP_WAIT(1); }
        else                    { CP_WAIT(0); }
        __syncthreads();
        if (kc + 3 < NKCH) {
            fill_stage(sb + (uint32_t)(((kc + 3) % NSTAGE) * STAGE_BYTES),
                       Ag, tileM, tileN, kc + 3, tid);
            CP_COMMIT();
        }
        uint32_t st = sb + (uint32_t)((kc % NSTAGE) * STAGE_BYTES);
        uint32_t aBase = st, bBase = st + A_BYTES;
        const int aRowB = warpM * 64 + (lane & 15);
        const int bRowB = warpN * 32 + ((lane >> 4) << 3) + (lane & 7);
        #pragma unroll
        for (int ks = 0; ks < 4; ks++) {
            const int u = ks * 2;
            const int aU = u + (lane >> 4);
            const int bU = u + ((lane >> 3) & 1);
            uint32_t af[4][4], bf[4][2];
            #pragma unroll
            for (int mi = 0; mi < 4; mi++)
                ldsm4(af[mi], sw_addr(aBase, aRowB + mi * 16, aU));
            #pragma unroll
            for (int nb = 0; nb < 2; nb++) {
                uint32_t r[4];
                ldsm4(r, sw_addr(bBase, bRowB + nb * 16, bU));
                bf[nb * 2 + 0][0] = r[0]; bf[nb * 2 + 0][1] = r[1];
                bf[nb * 2 + 1][0] = r[2]; bf[nb * 2 + 1][1] = r[3];
            }
            #pragma unroll
            for (int mi = 0; mi < 4; mi++)
                #pragma unroll
                for (int ni = 0; ni < 4; ni++)
                    mma16816(acc[mi][ni], af[mi], bf[ni]);
        }
    }

    // store result rows — single base pointer per CTA
    {
        float* outb = (MODE == 0) ? score_row(tileM * BM) : G_row(tileM * BM);
        #pragma unroll
        for (int mi = 0; mi < 4; mi++) {
            #pragma unroll
            for (int ni = 0; ni < 4; ni++) {
                int lr = warpM * 64 + mi * 16 + grp;
                int c0 = tileN * BN + warpN * 32 + ni * 8 + qc * 2;
                *(float2*)&outb[(size_t)lr * K_CB + c0] =
                    make_float2(acc[mi][ni][0], acc[mi][ni][1]);
                *(float2*)&outb[(size_t)(lr + 8) * K_CB + c0] =
                    make_float2(acc[mi][ni][2], acc[mi][ni][3]);
            }
        }
    }

    if (MODE == 1) return;

    __syncthreads();
    float* sv1 = (float*)smem;                       // [256][4]
    int*   si1 = (int*)(smem + 4096);
    float* sv2 = (float*)(smem + 8192);
    int*   si2 = (int*)(smem + 12288);

    #pragma unroll
    for (int mi = 0; mi < 4; mi++) {
        Top2 lo = {-3.4e38f, 0x7fffffff, -3.4e38f, 0x7fffffff};
        Top2 hi = {-3.4e38f, 0x7fffffff, -3.4e38f, 0x7fffffff};
        #pragma unroll
        for (int ni = 0; ni < 4; ni++) {
            #pragma unroll
            for (int j = 0; j < 2; j++) {
                int c = warpN * 32 + ni * 8 + qc * 2 + j;
                t2_insert(lo, acc[mi][ni][j], c);
                t2_insert(hi, acc[mi][ni][2 + j], c);
            }
        }
        #pragma unroll
        for (int off = 1; off < 4; off <<= 1) {
            Top2 o;
            o.v1 = __shfl_xor_sync(0xffffffffu, lo.v1, off);
            o.i1 = __shfl_xor_sync(0xffffffffu, lo.i1, off);
            o.v2 = __shfl_xor_sync(0xffffffffu, lo.v2, off);
            o.i2 = __shfl_xor_sync(0xffffffffu, lo.i2, off);
            t2_merge(lo, o);
            o.v1 = __shfl_xor_sync(0xffffffffu, hi.v1, off);
            o.i1 = __shfl_xor_sync(0xffffffffu, hi.i1, off);
            o.v2 = __shfl_xor_sync(0xffffffffu, hi.v2, off);
            o.i2 = __shfl_xor_sync(0xffffffffu, hi.i2, off);
            t2_merge(hi, o);
        }
        if (qc == 0) {
            int rLo = warpM * 64 + mi * 16 + grp;
            sv1[rLo * 4 + warpN] = lo.v1;  si1[rLo * 4 + warpN] = lo.i1;
            sv2[rLo * 4 + warpN] = lo.v2;  si2[rLo * 4 + warpN] = lo.i2;
            int rHi = rLo + 8;
            sv1[rHi * 4 + warpN] = hi.v1;  si1[rHi * 4 + warpN] = hi.i1;
            sv2[rHi * 4 + warpN] = hi.v2;  si2[rHi * 4 + warpN] = hi.i2;
        }
    }
    __syncthreads();
    if (tid < 256) {
        Top2 t = {sv1[tid * 4], si1[tid * 4], sv2[tid * 4], si2[tid * 4]};
        #pragma unroll
        for (int w = 1; w < 4; w++) {
            Top2 o = {sv1[tid * 4 + w], si1[tid * 4 + w],
                      sv2[tid * 4 + w], si2[tid * 4 + w]};
            t2_merge(t, o);
        }
        size_t oo = (size_t)(tileM * BM + tid) * NT + tileN;
        g_t1v[oo] = t.v1;  g_t1i[oo] = tileN * BN + t.i1;
        g_t2v[oo] = t.v2;  g_t2i[oo] = tileN * BN + t.i2;
    }
}

// ============================================================
// mirror v2 (FIXED): one CTA per 64x64 sub-block of the lower wedge.
// dest block rows [bx*64,+64), cols [by*64,+64); source is transpose.
// ============================================================
__global__ void __launch_bounds__(256, 4) mirror_kernel() {
    int bx = blockIdx.x, by = blockIdx.y;
    int tileM = bx >> 2, tileN = by >> 1;
    if (tileN >= 2 * tileM) return;        // dest was computed directly

    __shared__ float t[64][65];
    int r0 = bx * 64, c0 = by * 64;
    int tx = threadIdx.x & 63;             // col within block
    int ty = threadIdx.x >> 6;             // 4 rows per pass

    // load source G[c0+row][r0+col] (kept region), coalesced in tx
    #pragma unroll
    for (int p = 0; p < 16; p++) {
        int row = p * 4 + ty;
        t[row][tx] = G_row(c0 + row)[r0 + tx];
    }
    __syncthreads();
    // store dest G[r0+row][c0+col] = t[col][row], coalesced in tx
    #pragma unroll
    for (int p = 0; p < 16; p++) {
        int row = p * 4 + ty;
        G_row(r0 + row)[c0 + tx] = t[tx][row];
    }
}

// ============================================================
// select step 0 / steps >= 1
// ============================================================
__global__ void select_tiles_kernel() {
    int tid = threadIdx.x, lane = tid & 31, wid = tid >> 5;
    int r = blockIdx.x * 8 + wid;
    size_t o = (size_t)r * NT + lane;
    float v1 = g_t1v[o];
    int   i1 = g_t1i[o];
    float v2 = g_t2v[o];
    #pragma unroll
    for (int off = 16; off > 0; off >>= 1) {
        float ov1 = __shfl_xor_sync(0xffffffffu, v1, off);
        int   oi1 = __shfl_xor_sync(0xffffffffu, i1, off);
        float ov2 = __shfl_xor_sync(0xffffffffu, v2, off);
        if (ov1 > v1 || (ov1 == v1 && oi1 < i1)) {
            v2 = fmaxf(ov2, v1);
            v1 = ov1; i1 = oi1;
        } else {
            v2 = fmaxf(v2, ov1);
        }
    }
    if (lane == 0) {
        g_choice[r] = i1;
        g_rowt1v[r] = v1;
        if (v1 - v2 < THR) {
            int p = atomicAdd(&g_flagcnt, 1);
            g_flaglist[p] = r;
        }
    }
}

__global__ void select_rows_kernel() {
    int r = blockIdx.x * 256 + threadIdx.x;
    if (r >= B_ROWS) return;
    g_choice[r] = g_rowt1i[r];
    if (g_rowt1v[r] - g_rowt2v[r] < THR) {
        int p = atomicAdd(&g_flagcnt, 1);
        g_flaglist[p] = r;
    }
}

// ============================================================
// refine: flagged rows, exact Kahan dots on candidates
// ============================================================
__global__ void refine_kernel(const float* __restrict__ cb) {
    __shared__ float sres[D_DIM];
    __shared__ int scand[128];
    __shared__ int scnt;
    __shared__ float sbv[8];
    __shared__ int   sbi[8];
    int tid = threadIdx.x, lane = tid & 31, wid = tid >> 5;
    int cnt = *(volatile int*)&g_flagcnt;

    for (int f = blockIdx.x; f < cnt; f += gridDim.x) {
        int r = g_flaglist[f];
        ((float4*)sres)[tid] = ((const float4*)(g_resid + (size_t)r * D_DIM))[tid];
        if (tid == 0) scnt = 0;
        __syncthreads();

        float thr = g_rowt1v[r] - THR;
        const float4* sc = (const float4*)score_row(r);
        #pragma unroll
        for (int i = 0; i < 4; i++) {
            int e = i * 256 + tid;
            float4 v = sc[e];
            int k = e * 4;
            if (v.x > thr) { int p = atomicAdd(&scnt, 1); if (p < 128) scand[p] = k; }
            if (v.y > thr) { int p = atomicAdd(&scnt, 1); if (p < 128) scand[p] = k + 1; }
            if (v.z > thr) { int p = atomicAdd(&scnt, 1); if (p < 128) scand[p] = k + 2; }
            if (v.w > thr) { int p = atomicAdd(&scnt, 1); if (p < 128) scand[p] = k + 3; }
        }
        __syncthreads();
        int nc = min(scnt, 128);

        float bv = -3.4e38f; int bi = 0x7fffffff;
        for (int c = wid; c < nc; c += 8) {
            int k = scand[c];
            const float* cbr = cb + (size_t)k * D_DIM;
            float s = 0.f, comp = 0.f;
            for (int e = lane; e < D_DIM; e += 32) {
                float prod = sres[e] * cbr[e];
                float y = prod - comp;
                float t = s + y;
                comp = (t - s) - y;
                s = t;
            }
            #pragma unroll
            for (int off = 16; off > 0; off >>= 1)
                s += __shfl_xor_sync(0xffffffffu, s, off);
            if (s > bv || (s == bv && k < bi)) { bv = s; bi = k; }
        }
        if (lane == 0) { sbv[wid] = bv; sbi[wid] = bi; }
        __syncthreads();
        if (tid == 0) {
            float v = sbv[0]; int i = sbi[0];
            #pragma unroll
            for (int w = 1; w < 8; w++)
                if (sbv[w] > v || (sbv[w] == v && sbi[w] < i)) { v = sbv[w]; i = sbi[w]; }
            g_choice[r] = i;
        }
        __syncthreads();
    }
}

// ============================================================
// fused step (512 threads): gate + index + residual update + norm +
// (if not last) score recurrence + next-step per-row top-2
// ============================================================
__global__ void __launch_bounds__(512) step_kernel(const float* __restrict__ cb,
                                                   int step, float decay, int last) {
    int r = blockIdx.x;
    int tid = threadIdx.x, lane = tid & 31, wid = tid >> 5;  // 16 warps
    __shared__ int s_idx, s_act;
    __shared__ float wsum[16];
    __shared__ float wv1[16]; __shared__ int wi1[16]; __shared__ float wv2[16];

    if (r == 0 && tid == 0) g_flagcnt = 0;

    if (tid == 0) {
        int i = g_choice[r];
        int act = g_active[r] && (sqrtf(g_norm2[r]) >= RES_TH);
        g_active[r] = act;
        g_indices[(size_t)r * L_STEPS + step] = act ? i : -1;
        s_idx = i;
        s_act = act;
    }
    __syncthreads();
    if (!s_act) return;

    int idx = s_idx;

    // --- residual update (exact fp32 per-element chain), float2 per thread ---
    {
        float2* r2 = (float2*)(g_resid + (size_t)r * D_DIM);
        const float2* c2 = (const float2*)(cb + (size_t)idx * D_DIM);
        float2 v = r2[tid];
        float2 c = c2[tid];
        v.x = __fsub_rn(v.x, __fmul_rn(decay, c.x));
        v.y = __fsub_rn(v.y, __fmul_rn(decay, c.y));
        r2[tid] = v;
        float local = v.x * v.x + v.y * v.y;
        #pragma unroll
        for (int off = 16; off > 0; off >>= 1)
            local += __shfl_xor_sync(0xffffffffu, local, off);
        if (lane == 0) wsum[wid] = local;
    }
    __syncthreads();
    if (tid == 0) {
        float s = 0.f;
        #pragma unroll
        for (int w = 0; w < 16; w++) s += wsum[w];
        g_norm2[r] = s;
    }

    if (last) return;

    // --- score recurrence + next-step top-2 ---
    const float4* G4 = (const float4*)G_row(idx);
    float4* sc = (float4*)score_row(r);

    float v1 = -3.4e38f; int i1 = 0x7fffffff; float v2 = -3.4e38f;
    #pragma unroll
    for (int i = 0; i < 2; i++) {
        int e = i * 512 + tid;
        float4 v = sc[e];
        float4 g = G4[e];
        v.x -= decay * g.x;
        v.y -= decay * g.y;
        v.z -= decay * g.z;
        v.w -= decay * g.w;
        sc[e] = v;
        int k = e * 4;
        if (v.x > v1 || (v.x == v1 && k < i1)) { v2 = v1; v1 = v.x; i1 = k; }
        else v2 = fmaxf(v2, v.x);
        if (v.y > v1 || (v.y == v1 && k + 1 < i1)) { v2 = v1; v1 = v.y; i1 = k + 1; }
        else v2 = fmaxf(v2, v.y);
        if (v.z > v1 || (v.z == v1 && k + 2 < i1)) { v2 = v1; v1 = v.z; i1 = k + 2; }
        else v2 = fmaxf(v2, v.z);
        if (v.w > v1 || (v.w == v1 && k + 3 < i1)) { v2 = v1; v1 = v.w; i1 = k + 3; }
        else v2 = fmaxf(v2, v.w);
    }
    #pragma unroll
    for (int off = 16; off > 0; off >>= 1) {
        float ov1 = __shfl_xor_sync(0xffffffffu, v1, off);
        int   oi1 = __shfl_xor_sync(0xffffffffu, i1, off);
        float ov2 = __shfl_xor_sync(0xffffffffu, v2, off);
        if (ov1 > v1 || (ov1 == v1 && oi1 < i1)) {
            v2 = fmaxf(v1, ov2);
            v1 = ov1; i1 = oi1;
        } else {
            v2 = fmaxf(v2, ov1);
        }
    }
    if (lane == 0) { wv1[wid] = v1; wi1[wid] = i1; wv2[wid] = v2; }
    __syncthreads();
    if (tid == 0) {
        float bv1 = wv1[0]; int bi1 = wi1[0]; float bv2 = wv2[0];
        #pragma unroll
        for (int w = 1; w < 16; w++) {
            if (wv1[w] > bv1 || (wv1[w] == bv1 && wi1[w] < bi1)) {
                bv2 = fmaxf(bv1, wv2[w]);
                bv1 = wv1[w]; bi1 = wi1[w];
            } else {
                bv2 = fmaxf(bv2, wv1[w]);
            }
        }
        g_rowt1v[r] = bv1;
        g_rowt1i[r] = bi1;
        g_rowt2v[r] = bv2;
    }
}

// ============================================================
// init / split
// ============================================================
__global__ void split_cb_kernel(const float* __restrict__ cb) {
    int r = blockIdx.x;
    const float4* c4 = (const float4*)(cb + (size_t)r * D_DIM);
    __half2* h0p = (__half2*)(g_cb0 + (size_t)r * D_DIM);
    int tid = threadIdx.x;
    float4 v = c4[tid];
    h0p[tid * 2 + 0] = __float22half2_rn(make_float2(v.x, v.y));
    h0p[tid * 2 + 1] = __float22half2_rn(make_float2(v.z, v.w));
}

__global__ void init_kernel(const float* __restrict__ targets) {
    int r = blockIdx.x;
    int tid = threadIdx.x;
    int lane = tid & 31, wid = tid >> 5;
    __shared__ float wsum[8];

    const float4* t4 = (const float4*)(targets + (size_t)r * D_DIM);
    float4* r4 = (float4*)(g_resid + (size_t)r * D_DIM);
    __half2* h0p = (__half2*)(g_rh0 + (size_t)r * D_DIM);

    float4 v = t4[tid];
    r4[tid] = v;
    h0p[tid * 2 + 0] = __float22half2_rn(make_float2(v.x, v.y));
    h0p[tid * 2 + 1] = __float22half2_rn(make_float2(v.z, v.w));

    float local = v.x * v.x + v.y * v.y + v.z * v.z + v.w * v.w;
    #pragma unroll
    for (int off = 16; off > 0; off >>= 1)
        local += __shfl_xor_sync(0xffffffffu, local, off);
    if (lane == 0) wsum[wid] = local;
    __syncthreads();
    if (tid == 0) {
        float s = 0.f;
        #pragma unroll
        for (int w = 0; w < 8; w++) s += wsum[w];
        g_norm2[r] = s;
        g_active[r] = 1;
    }
}

// ============================================================
// finalize variants
// ============================================================
__global__ void out_both_f32(float* __restrict__ out) {
    int r = blockIdx.x;
    for (int c = threadIdx.x; c < D_DIM; c += 256)
        out[(size_t)B_ROWS * L_STEPS + (size_t)r * D_DIM + c] = g_resid[(size_t)r * D_DIM + c];
    if (threadIdx.x < L_STEPS)
        out[(size_t)r * L_STEPS + threadIdx.x] = (float)g_indices[(size_t)r * L_STEPS + threadIdx.x];
}
__global__ void out_idx_i32(int* __restrict__ out) {
    int i = blockIdx.x * 256 + threadIdx.x;
    if (i < B_ROWS * L_STEPS) out[i] = g_indices[i];
}
__global__ void out_res_f32(float* __restrict__ out) {
    int r = blockIdx.x;
    for (int c = threadIdx.x; c < D_DIM; c += 256)
        out[(size_t)r * D_DIM + c] = g_resid[(size_t)r * D_DIM + c];
}

// ============================================================
// host launcher
// ============================================================
extern "C" void kernel_launch(void* const* d_in, const int* in_sizes, int n_in,
                              void* d_out, int out_size) {
    const float* targets  = (const float*)d_in[0];
    const float* codebook = (const float*)d_in[1];

    cudaFuncSetAttribute(gemm_kernel<0>,
                         cudaFuncAttributeMaxDynamicSharedMemorySize, SMEM_TOTAL);
    cudaFuncSetAttribute(gemm_kernel<1>,
                         cudaFuncAttributeMaxDynamicSharedMemorySize, SMEM_TOTAL);

    split_cb_kernel<<<K_CB, 256>>>(codebook);
    init_kernel<<<B_ROWS, 256>>>(targets);

    {   // Gram matrix G = cb @ cb^T (upper wedge only) + mirror
        dim3 grid(K_CB / BM, K_CB / BN);
        gemm_kernel<1><<<grid, 512, SMEM_TOTAL>>>();
        dim3 mgrid(K_CB / 64, K_CB / 64);
        mirror_kernel<<<mgrid, 256>>>();
    }
    {   // initial scores = targets @ cb^T + per-tile top-2
        dim3 grid(B_ROWS / BM, K_CB / BN);
        gemm_kernel<0><<<grid, 512, SMEM_TOTAL>>>();
    }

    for (int s = 0; s < L_STEPS; s++) {
        if (s == 0) select_tiles_kernel<<<B_ROWS / 8, 256>>>();
        else        select_rows_kernel<<<B_ROWS / 256, 256>>>();
        refine_kernel<<<128, 256>>>(codebook);
        float decay = (float)pow(0.9, (double)s);
        step_kernel<<<B_ROWS, 512>>>(codebook, s, decay, s + 1 == L_STEPS);
    }

    if (out_size == B_ROWS * L_STEPS) {
        out_idx_i32<<<(B_ROWS * L_STEPS + 255) / 256, 256>>>((int*)d_out);
    } else if (out_size == B_ROWS * D_DIM) {
        out_res_f32<<<B_ROWS, 256>>>((float*)d_out);
    } else {
        out_both_f32<<<B_ROWS, 256>>>((float*)d_out);
    }
}

// round 15
// speedup vs baseline: 1.0804x; 1.0804x over previous
#include <cuda_runtime.h>
#include <cuda_fp16.h>
#include <cstdint>
#include <math.h>

// ============================================================
// Problem constants
// ============================================================
#define B_ROWS 8192
#define D_DIM  1024
#define K_CB   4096
#define L_STEPS 8
#define RES_TH 1e-3f
#define THR    0.40f

// GEMM tiling: CTA 256x128, 512 threads, 16 warps (4M x 4N), warp tile 64x32
#define BM 256
#define BN 128
#define BK 64
#define NT    (K_CB / BN)     // 32
#define NKCH  (D_DIM / BK)    // 16
#define NSTAGE 4
#define A_BYTES (BM * BK * 2)
#define B_BYTES (BN * BK * 2)
#define STAGE_BYTES (A_BYTES + B_BYTES)        // 49152
#define SMEM_TOTAL  (NSTAGE * STAGE_BYTES)     // 196608

// ============================================================
// Device scratch — every array <= 32 MB
// ============================================================
__device__ __align__(128) float  g_resid[B_ROWS * D_DIM];            // 32 MB
__device__ __align__(128) __half g_rh0[B_ROWS * D_DIM];              // 16 MB
__device__ __align__(128) __half g_cb0[K_CB * D_DIM];                // 8 MB
#define SC_CHUNK_ROWS 2048
__device__ __align__(128) float g_sc0[SC_CHUNK_ROWS * K_CB];         // 32 MB x4
__device__ __align__(128) float g_sc1[SC_CHUNK_ROWS * K_CB];
__device__ __align__(128) float g_sc2[SC_CHUNK_ROWS * K_CB];
__device__ __align__(128) float g_sc3[SC_CHUNK_ROWS * K_CB];
__device__ __align__(128) float g_G0[SC_CHUNK_ROWS * K_CB];          // 32 MB x2
__device__ __align__(128) float g_G1[SC_CHUNK_ROWS * K_CB];

__device__ float g_t1v[B_ROWS * NT];
__device__ int   g_t1i[B_ROWS * NT];
__device__ float g_t2v[B_ROWS * NT];
__device__ int   g_t2i[B_ROWS * NT];
__device__ float g_rowt1v[B_ROWS];
__device__ int   g_rowt1i[B_ROWS];
__device__ float g_rowt2v[B_ROWS];
__device__ float g_norm2[B_ROWS];
__device__ int   g_active[B_ROWS];
__device__ int   g_indices[B_ROWS * L_STEPS];
__device__ int   g_choice[B_ROWS];
__device__ int   g_flagcnt;
__device__ int   g_flaglist[B_ROWS];

__device__ __forceinline__ float* score_row(int r) {
    int c = r >> 11;
    float* b = (c == 0) ? g_sc0 : (c == 1) ? g_sc1 : (c == 2) ? g_sc2 : g_sc3;
    return b + (size_t)(r & (SC_CHUNK_ROWS - 1)) * K_CB;
}
__device__ __forceinline__ float* G_row(int k) {
    float* b = (k >> 11) ? g_G1 : g_G0;
    return b + (size_t)(k & (SC_CHUNK_ROWS - 1)) * K_CB;
}

// ============================================================
// PTX helpers
// ============================================================
__device__ __forceinline__ uint32_t smem_u32(const void* p) {
    uint32_t a;
    asm("{ .reg .u64 t; cvta.to.shared.u64 t, %1; cvt.u32.u64 %0, t; }"
        : "=r"(a) : "l"(p));
    return a;
}
__device__ __forceinline__ void cp16(uint32_t s, const void* g) {
    asm volatile("cp.async.cg.shared.global [%0], [%1], 16;" :: "r"(s), "l"(g));
}
#define CP_COMMIT() asm volatile("cp.async.commit_group;" ::: "memory")
#define CP_WAIT(n)  asm volatile("cp.async.wait_group %0;" :: "n"(n) : "memory")

__device__ __forceinline__ void ldsm4(uint32_t* r, uint32_t addr) {
    asm volatile("ldmatrix.sync.aligned.m8n8.x4.shared.b16 {%0,%1,%2,%3}, [%4];"
        : "=r"(r[0]), "=r"(r[1]), "=r"(r[2]), "=r"(r[3]) : "r"(addr));
}
__device__ __forceinline__ void mma16816(float* c, const uint32_t* a, const uint32_t* b) {
    asm volatile(
        "mma.sync.aligned.m16n8k16.row.col.f32.f16.f16.f32 "
        "{%0,%1,%2,%3}, {%4,%5,%6,%7}, {%8,%9}, {%0,%1,%2,%3};"
        : "+f"(c[0]), "+f"(c[1]), "+f"(c[2]), "+f"(c[3])
        : "r"(a[0]), "r"(a[1]), "r"(a[2]), "r"(a[3]), "r"(b[0]), "r"(b[1]));
}
__device__ __forceinline__ uint32_t sw_addr(uint32_t base, int row, int unit) {
    return base + (uint32_t)(row * 128) + (uint32_t)((unit ^ (row & 7)) << 4);
}

struct Top2 { float v1; int i1; float v2; int i2; };
__device__ __forceinline__ void t2_insert(Top2& t, float v, int c) {
    if (v > t.v1 || (v == t.v1 && c < t.i1)) {
        t.v2 = t.v1; t.i2 = t.i1; t.v1 = v; t.i1 = c;
    } else if (v > t.v2 || (v == t.v2 && c < t.i2)) {
        t.v2 = v; t.i2 = c;
    }
}
__device__ __forceinline__ void t2_merge(Top2& a, const Top2& b) {
    if (b.v1 > a.v1 || (b.v1 == a.v1 && b.i1 < a.i1)) {
        if (a.v1 > b.v2 || (a.v1 == b.v2 && a.i1 < b.i2)) { a.v2 = a.v1; a.i2 = a.i1; }
        else { a.v2 = b.v2; a.i2 = b.i2; }
        a.v1 = b.v1; a.i1 = b.i1;
    } else {
        if (b.v1 > a.v2 || (b.v1 == a.v2 && b.i1 < a.i2)) { a.v2 = b.v1; a.i2 = b.i1; }
    }
}

// ============================================================
// Unified GEMM: MODE 0 -> scores + per-tile top-2; MODE 1 -> Gram fp32
// MODE 1 computes only tiles with tileN >= 2*tileM; mirror fills rest.
// ============================================================
__device__ __forceinline__ void fill_stage(uint32_t st, const __half* Ag,
                                           int tileM, int tileN, int kc, int tid) {
    const __half* a0 = Ag + ((size_t)tileM * BM) * D_DIM + kc * BK;
    const __half* b0 = g_cb0 + ((size_t)tileN * BN) * D_DIM + kc * BK;
    #pragma unroll
    for (int i = 0; i < 4; i++) {
        int c = tid + i * 512;
        int row = c >> 3, u = c & 7;
        uint32_t sw = (uint32_t)(row * 128) + (uint32_t)((u ^ (row & 7)) << 4);
        cp16(st + sw, a0 + (size_t)row * D_DIM + (u << 3));
    }
    #pragma unroll
    for (int i = 0; i < 2; i++) {
        int c = tid + i * 512;
        int row = c >> 3, u = c & 7;
        uint32_t sw = (uint32_t)(row * 128) + (uint32_t)((u ^ (row & 7)) << 4);
        cp16(st + A_BYTES + sw, b0 + (size_t)row * D_DIM + (u << 3));
    }
}

template <int MODE>
__global__ void __launch_bounds__(512, 1) gemm_kernel() {
    extern __shared__ char smem[];
    uint32_t sb = smem_u32(smem);
    const int tid = threadIdx.x;
    const int tileM = blockIdx.x, tileN = blockIdx.y;
    const int wid = tid >> 5, lane = tid & 31;
    const int warpM = wid >> 2, warpN = wid & 3;
    const int grp = lane >> 2, qc = lane & 3;

    if (MODE == 1 && tileN < 2 * tileM) return;   // symmetry: skip lower wedge

    const __half* Ag = (MODE == 0) ? g_rh0 : g_cb0;

    if (MODE == 0 && tileM == 0 && tileN == 0 && tid == 0) g_flagcnt = 0;

    float acc[4][4][4];
    #pragma unroll
    for (int mi = 0; mi < 4; mi++)
        #pragma unroll
        for (int ni = 0; ni < 4; ni++)
            #pragma unroll
            for (int j = 0; j < 4; j++) acc[mi][ni][j] = 0.f;

    fill_stage(sb, Ag, tileM, tileN, 0, tid);                      CP_COMMIT();
    fill_stage(sb + STAGE_BYTES, Ag, tileM, tileN, 1, tid);        CP_COMMIT();
    fill_stage(sb + 2 * STAGE_BYTES, Ag, tileM, tileN, 2, tid);    CP_COMMIT();

    #pragma unroll 1
    for (int kc = 0; kc < NKCH; kc++) {
        if (kc < NKCH - 2)      { CP_WAIT(2); }
        else if (kc == NKCH - 2){ CP_WAIT(1); }
        else                    { CP_WAIT(0); }
        __syncthreads();
        if (kc + 3 < NKCH) {
            fill_stage(sb + (uint32_t)(((kc + 3) % NSTAGE) * STAGE_BYTES),
                       Ag, tileM, tileN, kc + 3, tid);
            CP_COMMIT();
        }
        uint32_t st = sb + (uint32_t)((kc % NSTAGE) * STAGE_BYTES);
        uint32_t aBase = st, bBase = st + A_BYTES;
        const int aRowB = warpM * 64 + (lane & 15);
        const int bRowB = warpN * 32 + ((lane >> 4) << 3) + (lane & 7);
        #pragma unroll
        for (int ks = 0; ks < 4; ks++) {
            const int u = ks * 2;
            const int aU = u + (lane >> 4);
            const int bU = u + ((lane >> 3) & 1);
            uint32_t af[4][4], bf[4][2];
            #pragma unroll
            for (int mi = 0; mi < 4; mi++)
                ldsm4(af[mi], sw_addr(aBase, aRowB + mi * 16, aU));
            #pragma unroll
            for (int nb = 0; nb < 2; nb++) {
                uint32_t r[4];
                ldsm4(r, sw_addr(bBase, bRowB + nb * 16, bU));
                bf[nb * 2 + 0][0] = r[0]; bf[nb * 2 + 0][1] = r[1];
                bf[nb * 2 + 1][0] = r[2]; bf[nb * 2 + 1][1] = r[3];
            }
            #pragma unroll
            for (int mi = 0; mi < 4; mi++)
                #pragma unroll
                for (int ni = 0; ni < 4; ni++)
                    mma16816(acc[mi][ni], af[mi], bf[ni]);
        }
    }

    // store result rows — single base pointer per CTA
    {
        float* outb = (MODE == 0) ? score_row(tileM * BM) : G_row(tileM * BM);
        #pragma unroll
        for (int mi = 0; mi < 4; mi++) {
            #pragma unroll
            for (int ni = 0; ni < 4; ni++) {
                int lr = warpM * 64 + mi * 16 + grp;
                int c0 = tileN * BN + warpN * 32 + ni * 8 + qc * 2;
                *(float2*)&outb[(size_t)lr * K_CB + c0] =
                    make_float2(acc[mi][ni][0], acc[mi][ni][1]);
                *(float2*)&outb[(size_t)(lr + 8) * K_CB + c0] =
                    make_float2(acc[mi][ni][2], acc[mi][ni][3]);
            }
        }
    }

    if (MODE == 1) return;

    __syncthreads();
    float* sv1 = (float*)smem;                       // [256][4]
    int*   si1 = (int*)(smem + 4096);
    float* sv2 = (float*)(smem + 8192);
    int*   si2 = (int*)(smem + 12288);

    #pragma unroll
    for (int mi = 0; mi < 4; mi++) {
        Top2 lo = {-3.4e38f, 0x7fffffff, -3.4e38f, 0x7fffffff};
        Top2 hi = {-3.4e38f, 0x7fffffff, -3.4e38f, 0x7fffffff};
        #pragma unroll
        for (int ni = 0; ni < 4; ni++) {
            #pragma unroll
            for (int j = 0; j < 2; j++) {
                int c = warpN * 32 + ni * 8 + qc * 2 + j;
                t2_insert(lo, acc[mi][ni][j], c);
                t2_insert(hi, acc[mi][ni][2 + j], c);
            }
        }
        #pragma unroll
        for (int off = 1; off < 4; off <<= 1) {
            Top2 o;
            o.v1 = __shfl_xor_sync(0xffffffffu, lo.v1, off);
            o.i1 = __shfl_xor_sync(0xffffffffu, lo.i1, off);
            o.v2 = __shfl_xor_sync(0xffffffffu, lo.v2, off);
            o.i2 = __shfl_xor_sync(0xffffffffu, lo.i2, off);
            t2_merge(lo, o);
            o.v1 = __shfl_xor_sync(0xffffffffu, hi.v1, off);
            o.i1 = __shfl_xor_sync(0xffffffffu, hi.i1, off);
            o.v2 = __shfl_xor_sync(0xffffffffu, hi.v2, off);
            o.i2 = __shfl_xor_sync(0xffffffffu, hi.i2, off);
            t2_merge(hi, o);
        }
        if (qc == 0) {
            int rLo = warpM * 64 + mi * 16 + grp;
            sv1[rLo * 4 + warpN] = lo.v1;  si1[rLo * 4 + warpN] = lo.i1;
            sv2[rLo * 4 + warpN] = lo.v2;  si2[rLo * 4 + warpN] = lo.i2;
            int rHi = rLo + 8;
            sv1[rHi * 4 + warpN] = hi.v1;  si1[rHi * 4 + warpN] = hi.i1;
            sv2[rHi * 4 + warpN] = hi.v2;  si2[rHi * 4 + warpN] = hi.i2;
        }
    }
    __syncthreads();
    if (tid < 256) {
        Top2 t = {sv1[tid * 4], si1[tid * 4], sv2[tid * 4], si2[tid * 4]};
        #pragma unroll
        for (int w = 1; w < 4; w++) {
            Top2 o = {sv1[tid * 4 + w], si1[tid * 4 + w],
                      sv2[tid * 4 + w], si2[tid * 4 + w]};
            t2_merge(t, o);
        }
        size_t oo = (size_t)(tileM * BM + tid) * NT + tileN;
        g_t1v[oo] = t.v1;  g_t1i[oo] = tileN * BN + t.i1;
        g_t2v[oo] = t.v2;  g_t2i[oo] = tileN * BN + t.i2;
    }
}

// ============================================================
// mirror v2: one CTA per 64x64 sub-block of the lower wedge.
// ============================================================
__global__ void __launch_bounds__(256, 4) mirror_kernel() {
    int bx = blockIdx.x, by = blockIdx.y;
    int tileM = bx >> 2, tileN = by >> 1;
    if (tileN >= 2 * tileM) return;        // dest was computed directly

    __shared__ float t[64][65];
    int r0 = bx * 64, c0 = by * 64;
    int tx = threadIdx.x & 63;
    int ty = threadIdx.x >> 6;

    #pragma unroll
    for (int p = 0; p < 16; p++) {
        int row = p * 4 + ty;
        t[row][tx] = G_row(c0 + row)[r0 + tx];
    }
    __syncthreads();
    #pragma unroll
    for (int p = 0; p < 16; p++) {
        int row = p * 4 + ty;
        G_row(r0 + row)[c0 + tx] = t[tx][row];
    }
}

// ============================================================
// select step 0 / steps >= 1
// ============================================================
__global__ void select_tiles_kernel() {
    int tid = threadIdx.x, lane = tid & 31, wid = tid >> 5;
    int r = blockIdx.x * 8 + wid;
    size_t o = (size_t)r * NT + lane;
    float v1 = g_t1v[o];
    int   i1 = g_t1i[o];
    float v2 = g_t2v[o];
    #pragma unroll
    for (int off = 16; off > 0; off >>= 1) {
        float ov1 = __shfl_xor_sync(0xffffffffu, v1, off);
        int   oi1 = __shfl_xor_sync(0xffffffffu, i1, off);
        float ov2 = __shfl_xor_sync(0xffffffffu, v2, off);
        if (ov1 > v1 || (ov1 == v1 && oi1 < i1)) {
            v2 = fmaxf(ov2, v1);
            v1 = ov1; i1 = oi1;
        } else {
            v2 = fmaxf(v2, ov1);
        }
    }
    if (lane == 0) {
        g_choice[r] = i1;
        g_rowt1v[r] = v1;
        if (v1 - v2 < THR) {
            int p = atomicAdd(&g_flagcnt, 1);
            g_flaglist[p] = r;
        }
    }
}

__global__ void select_rows_kernel() {
    int r = blockIdx.x * 256 + threadIdx.x;
    if (r >= B_ROWS) return;
    g_choice[r] = g_rowt1i[r];
    if (g_rowt1v[r] - g_rowt2v[r] < THR) {
        int p = atomicAdd(&g_flagcnt, 1);
        g_flaglist[p] = r;
    }
}

// ============================================================
// refine: flagged rows, exact Kahan dots on candidates
// ============================================================
__global__ void refine_kernel(const float* __restrict__ cb) {
    __shared__ float sres[D_DIM];
    __shared__ int scand[128];
    __shared__ int scnt;
    __shared__ float sbv[8];
    __shared__ int   sbi[8];
    int tid = threadIdx.x, lane = tid & 31, wid = tid >> 5;
    int cnt = *(volatile int*)&g_flagcnt;

    for (int f = blockIdx.x; f < cnt; f += gridDim.x) {
        int r = g_flaglist[f];
        ((float4*)sres)[tid] = ((const float4*)(g_resid + (size_t)r * D_DIM))[tid];
        if (tid == 0) scnt = 0;
        __syncthreads();

        float thr = g_rowt1v[r] - THR;
        const float4* sc = (const float4*)score_row(r);
        #pragma unroll
        for (int i = 0; i < 4; i++) {
            int e = i * 256 + tid;
            float4 v = sc[e];
            int k = e * 4;
            if (v.x > thr) { int p = atomicAdd(&scnt, 1); if (p < 128) scand[p] = k; }
            if (v.y > thr) { int p = atomicAdd(&scnt, 1); if (p < 128) scand[p] = k + 1; }
            if (v.z > thr) { int p = atomicAdd(&scnt, 1); if (p < 128) scand[p] = k + 2; }
            if (v.w > thr) { int p = atomicAdd(&scnt, 1); if (p < 128) scand[p] = k + 3; }
        }
        __syncthreads();
        int nc = min(scnt, 128);

        float bv = -3.4e38f; int bi = 0x7fffffff;
        for (int c = wid; c < nc; c += 8) {
            int k = scand[c];
            const float* cbr = cb + (size_t)k * D_DIM;
            float s = 0.f, comp = 0.f;
            for (int e = lane; e < D_DIM; e += 32) {
                float prod = sres[e] * cbr[e];
                float y = prod - comp;
                float t = s + y;
                comp = (t - s) - y;
                s = t;
            }
            #pragma unroll
            for (int off = 16; off > 0; off >>= 1)
                s += __shfl_xor_sync(0xffffffffu, s, off);
            if (s > bv || (s == bv && k < bi)) { bv = s; bi = k; }
        }
        if (lane == 0) { sbv[wid] = bv; sbi[wid] = bi; }
        __syncthreads();
        if (tid == 0) {
            float v = sbv[0]; int i = sbi[0];
            #pragma unroll
            for (int w = 1; w < 8; w++)
                if (sbv[w] > v || (sbv[w] == v && sbi[w] < i)) { v = sbv[w]; i = sbi[w]; }
            g_choice[r] = i;
        }
        __syncthreads();
    }
}

// ============================================================
// fused step (256 threads, round-12 validated form):
// gate + index + residual update + norm +
// (if not last) score recurrence + next-step per-row top-2
// ============================================================
__global__ void step_kernel(const float* __restrict__ cb, int step, float decay,
                            int last) {
    int r = blockIdx.x;
    int tid = threadIdx.x, lane = tid & 31, wid = tid >> 5;
    __shared__ int s_idx, s_act;
    __shared__ float wsum[8];
    __shared__ float wv1[8]; __shared__ int wi1[8]; __shared__ float wv2[8];

    if (r == 0 && tid == 0) g_flagcnt = 0;

    if (tid == 0) {
        int i = g_choice[r];
        int act = g_active[r] && (sqrtf(g_norm2[r]) >= RES_TH);
        g_active[r] = act;
        g_indices[(size_t)r * L_STEPS + step] = act ? i : -1;
        s_idx = i;
        s_act = act;
    }
    __syncthreads();
    if (!s_act) return;

    int idx = s_idx;

    // --- residual update (exact fp32 chain) ---
    {
        float4* r4 = (float4*)(g_resid + (size_t)r * D_DIM);
        const float4* c4 = (const float4*)(cb + (size_t)idx * D_DIM);
        float4 v = r4[tid];
        float4 c = c4[tid];
        v.x = __fsub_rn(v.x, __fmul_rn(decay, c.x));
        v.y = __fsub_rn(v.y, __fmul_rn(decay, c.y));
        v.z = __fsub_rn(v.z, __fmul_rn(decay, c.z));
        v.w = __fsub_rn(v.w, __fmul_rn(decay, c.w));
        r4[tid] = v;
        float local = v.x * v.x + v.y * v.y + v.z * v.z + v.w * v.w;
        #pragma unroll
        for (int off = 16; off > 0; off >>= 1)
            local += __shfl_xor_sync(0xffffffffu, local, off);
        if (lane == 0) wsum[wid] = local;
    }
    __syncthreads();
    if (tid == 0) {
        float s = 0.f;
        #pragma unroll
        for (int w = 0; w < 8; w++) s += wsum[w];
        g_norm2[r] = s;
    }

    if (last) return;

    // --- score recurrence + next-step top-2 ---
    const float4* G4 = (const float4*)G_row(idx);
    float4* sc = (float4*)score_row(r);

    float v1 = -3.4e38f; int i1 = 0x7fffffff; float v2 = -3.4e38f;
    #pragma unroll
    for (int i = 0; i < 4; i++) {
        int e = i * 256 + tid;
        float4 v = sc[e];
        float4 g = G4[e];
        v.x -= decay * g.x;
        v.y -= decay * g.y;
        v.z -= decay * g.z;
        v.w -= decay * g.w;
        sc[e] = v;
        int k = e * 4;
        if (v.x > v1 || (v.x == v1 && k < i1)) { v2 = v1; v1 = v.x; i1 = k; }
        else v2 = fmaxf(v2, v.x);
        if (v.y > v1 || (v.y == v1 && k + 1 < i1)) { v2 = v1; v1 = v.y; i1 = k + 1; }
        else v2 = fmaxf(v2, v.y);
        if (v.z > v1 || (v.z == v1 && k + 2 < i1)) { v2 = v1; v1 = v.z; i1 = k + 2; }
        else v2 = fmaxf(v2, v.z);
        if (v.w > v1 || (v.w == v1 && k + 3 < i1)) { v2 = v1; v1 = v.w; i1 = k + 3; }
        else v2 = fmaxf(v2, v.w);
    }
    #pragma unroll
    for (int off = 16; off > 0; off >>= 1) {
        float ov1 = __shfl_xor_sync(0xffffffffu, v1, off);
        int   oi1 = __shfl_xor_sync(0xffffffffu, i1, off);
        float ov2 = __shfl_xor_sync(0xffffffffu, v2, off);
        if (ov1 > v1 || (ov1 == v1 && oi1 < i1)) {
            v2 = fmaxf(v1, ov2);
            v1 = ov1; i1 = oi1;
        } else {
            v2 = fmaxf(v2, ov1);
        }
    }
    if (lane == 0) { wv1[wid] = v1; wi1[wid] = i1; wv2[wid] = v2; }
    __syncthreads();
    if (tid == 0) {
        float bv1 = wv1[0]; int bi1 = wi1[0]; float bv2 = wv2[0];
        #pragma unroll
        for (int w = 1; w < 8; w++) {
            if (wv1[w] > bv1 || (wv1[w] == bv1 && wi1[w] < bi1)) {
                bv2 = fmaxf(bv1, wv2[w]);
                bv1 = wv1[w]; bi1 = wi1[w];
            } else {
                bv2 = fmaxf(bv2, wv1[w]);
            }
        }
        g_rowt1v[r] = bv1;
        g_rowt1i[r] = bi1;
        g_rowt2v[r] = bv2;
    }
}

// ============================================================
// init / split
// ============================================================
__global__ void split_cb_kernel(const float* __restrict__ cb) {
    int r = blockIdx.x;
    const float4* c4 = (const float4*)(cb + (size_t)r * D_DIM);
    __half2* h0p = (__half2*)(g_cb0 + (size_t)r * D_DIM);
    int tid = threadIdx.x;
    float4 v = c4[tid];
    h0p[tid * 2 + 0] = __float22half2_rn(make_float2(v.x, v.y));
    h0p[tid * 2 + 1] = __float22half2_rn(make_float2(v.z, v.w));
}

__global__ void init_kernel(const float* __restrict__ targets) {
    int r = blockIdx.x;
    int tid = threadIdx.x;
    int lane = tid & 31, wid = tid >> 5;
    __shared__ float wsum[8];

    const float4* t4 = (const float4*)(targets + (size_t)r * D_DIM);
    float4* r4 = (float4*)(g_resid + (size_t)r * D_DIM);
    __half2* h0p = (__half2*)(g_rh0 + (size_t)r * D_DIM);

    float4 v = t4[tid];
    r4[tid] = v;
    h0p[tid * 2 + 0] = __float22half2_rn(make_float2(v.x, v.y));
    h0p[tid * 2 + 1] = __float22half2_rn(make_float2(v.z, v.w));

    float local = v.x * v.x + v.y * v.y + v.z * v.z + v.w * v.w;
    #pragma unroll
    for (int off = 16; off > 0; off >>= 1)
        local += __shfl_xor_sync(0xffffffffu, local, off);
    if (lane == 0) wsum[wid] = local;
    __syncthreads();
    if (tid == 0) {
        float s = 0.f;
        #pragma unroll
        for (int w = 0; w < 8; w++) s += wsum[w];
        g_norm2[r] = s;
        g_active[r] = 1;
    }
}

// ============================================================
// finalize variants
// ============================================================
__global__ void out_both_f32(float* __restrict__ out) {
    int r = blockIdx.x;
    for (int c = threadIdx.x; c < D_DIM; c += 256)
        out[(size_t)B_ROWS * L_STEPS + (size_t)r * D_DIM + c] = g_resid[(size_t)r * D_DIM + c];
    if (threadIdx.x < L_STEPS)
        out[(size_t)r * L_STEPS + threadIdx.x] = (float)g_indices[(size_t)r * L_STEPS + threadIdx.x];
}
__global__ void out_idx_i32(int* __restrict__ out) {
    int i = blockIdx.x * 256 + threadIdx.x;
    if (i < B_ROWS * L_STEPS) out[i] = g_indices[i];
}
__global__ void out_res_f32(float* __restrict__ out) {
    int r = blockIdx.x;
    for (int c = threadIdx.x; c < D_DIM; c += 256)
        out[(size_t)r * D_DIM + c] = g_resid[(size_t)r * D_DIM + c];
}

// ============================================================
// host launcher
// ============================================================
extern "C" void kernel_launch(void* const* d_in, const int* in_sizes, int n_in,
                              void* d_out, int out_size) {
    const float* targets  = (const float*)d_in[0];
    const float* codebook = (const float*)d_in[1];

    cudaFuncSetAttribute(gemm_kernel<0>,
                         cudaFuncAttributeMaxDynamicSharedMemorySize, SMEM_TOTAL);
    cudaFuncSetAttribute(gemm_kernel<1>,
                         cudaFuncAttributeMaxDynamicSharedMemorySize, SMEM_TOTAL);

    split_cb_kernel<<<K_CB, 256>>>(codebook);
    init_kernel<<<B_ROWS, 256>>>(targets);

    {   // Gram matrix G = cb @ cb^T (upper wedge only) + mirror
        dim3 grid(K_CB / BM, K_CB / BN);
        gemm_kernel<1><<<grid, 512, SMEM_TOTAL>>>();
        dim3 mgrid(K_CB / 64, K_CB / 64);
        mirror_kernel<<<mgrid, 256>>>();
    }
    {   // initial scores = targets @ cb^T + per-tile top-2
        dim3 grid(B_ROWS / BM, K_CB / BN);
        gemm_kernel<0><<<grid, 512, SMEM_TOTAL>>>();
    }

    for (int s = 0; s < L_STEPS; s++) {
        if (s == 0) select_tiles_kernel<<<B_ROWS / 8, 256>>>();
        else        select_rows_kernel<<<B_ROWS / 256, 256>>>();
        refine_kernel<<<128, 256>>>(codebook);
        float decay = (float)pow(0.9, (double)s);
        step_kernel<<<B_ROWS, 256>>>(codebook, s, decay, s + 1 == L_STEPS);
    }

    if (out_size == B_ROWS * L_STEPS) {
        out_idx_i32<<<(B_ROWS * L_STEPS + 255) / 256, 256>>>((int*)d_out);
    } else if (out_size == B_ROWS * D_DIM) {
        out_res_f32<<<B_ROWS, 256>>>((float*)d_out);
    } else {
        out_both_f32<<<B_ROWS, 256>>>((float*)d_out);
    }
}